// round 8
// baseline (speedup 1.0000x reference)
#include <cuda_runtime.h>
#include <cuda_fp16.h>
#include <cstdint>

// ============================================================================
// AWQ int4 linear via fp16 mma.sync (m16n8k16, fp32 accumulate):
//   (1) single merged prepass: dequant W + round x -> fp16 fragment tiles
//   (2) GEMM: 256x128 CTA tiles (512 thr, 16 warps), warp 64x32, k-chunk 64,
//       3-stage cp.async pipeline, conflict-free LDS.128 fragment loads.
// 256x128 tiling cuts L2 read traffic 25% vs 128x128 at identical tensor
// throughput per SM (4 warps/SMSP retained).
// out[m][n] = sum_k x[m][k]*W[n][k] + bias[n]
// W[n][k] = (q[n][k]*scales[g]+offsets[g])*inv_scale[k], g = n*32 + k/128
// M=8192, N=11008, K=4096.
// ============================================================================

#define IN_DIM   4096
#define OUT_DIM  11008
#define M_DIM    8192
#define BKC      64                    // k per pipeline stage
#define NKC      (IN_DIM / BKC)        // 64 k-chunks
#define STAGES   3
#define TILE_U32 4096                  // one 128x64 fp16 operand tile (16KB)
#define STAGE_U32 (3 * TILE_U32)       // A0, A1, B (48KB)
#define SMEM_BYTES (STAGES * STAGE_U32 * 4)   // 147456 (144KB)
#define MT_TILES  (M_DIM / 128)        // 64
#define MT2_TILES (M_DIM / 256)        // 32
#define NT_TILES  (OUT_DIM / 128)      // 86
#define W_TILES   (NT_TILES * NKC)     // 5504
#define X_TILES   (MT_TILES * NKC)     // 4096

// Pre-tiled fp16 operands in fragment order (static scratch; no allocs).
__device__ uint32_t g_w[(size_t)W_TILES * TILE_U32];   // 90 MB
__device__ uint32_t g_x[(size_t)X_TILES * TILE_U32];   // 67 MB

__device__ __forceinline__ uint32_t smem_u32(const void* p) {
    uint32_t a;
    asm("{ .reg .u64 t; cvta.to.shared.u64 t, %1; cvt.u32.u64 %0, t; }"
        : "=r"(a) : "l"(p));
    return a;
}

// ---- fragment-order u32 offsets within a 4096-u32 (128 x 64 fp16) tile ----
// A (x): vec v = wm*16 + ks*4 + b  (wm: m64-half, ks: k16-step, b: m16-block)
__device__ __forceinline__ int a_u32(int mm, int kk) {
    const int wm = mm >> 6, b = (mm >> 4) & 3, row = mm & 15;
    const int gid = row & 7, hi = row >> 3;
    const int ks = kk >> 4, kk16 = kk & 15;
    const int colhi = (kk16 >> 3) & 1, tig = (kk16 >> 1) & 3;
    const int v = wm * 16 + ks * 4 + b;
    return (v * 32 + gid * 4 + tig) * 4 + hi + 2 * colhi;
}
// B (W): vec = (wn*4 + ks)*2 + p  (wn: n32-quarter, p: nb pair)
__device__ __forceinline__ int b_u32(int nn, int kk) {
    const int wn = nn >> 5, nb = (nn >> 3) & 3, gid = nn & 7;
    const int ks = kk >> 4, kk16 = kk & 15;
    const int khi = (kk16 >> 3) & 1, tig = (kk16 >> 1) & 3;
    return ((((wn * 4 + ks) * 2 + (nb >> 1)) * 32) + gid * 4 + tig) * 4
           + (nb & 1) * 2 + khi;
}

__device__ __forceinline__ uint32_t pack_h2(float lo, float hi) {
    __half2 h = __floats2half2_rn(lo, hi);   // .x = lo half
    return *(uint32_t*)&h;
}

// ============================================================================
// Merged prepass: blocks [0, W_TILES) dequant W tiles; rest build x tiles.
// One block builds one 128x64 fragment-ordered tile in smem, writes coalesced.
// ============================================================================
__global__ __launch_bounds__(256)
void prep_kernel(const int* __restrict__ packed,
                 const float* __restrict__ scales,
                 const float* __restrict__ offsets,
                 const float* __restrict__ inv,
                 const float* __restrict__ x) {
    __shared__ uint32_t st[TILE_U32];
    const int tid = threadIdx.x;
    const int r = tid >> 1, h = tid & 1;   // row 0..127, half 0..1

    if (blockIdx.x < W_TILES) {
        const int tile = blockIdx.x;       // nT * NKC + kc
        const int nT = tile / NKC, kc = tile % NKC;
        const int n = nT * 128 + r;
        const int g = (n << 5) + (kc >> 1);
        const float s = __ldg(scales + g);
        const float o = __ldg(offsets + g);
        const int kbase = kc * 64 + h * 32;
        const int* src = packed + (size_t)n * 2048 + (kbase >> 1);

#pragma unroll
        for (int i = 0; i < 4; ++i) {
            const int4 u4 = *(const int4*)(src + i * 4);
            const int uv[4] = {u4.x, u4.y, u4.z, u4.w};
#pragma unroll
            for (int j = 0; j < 4; ++j) {
                const int u = uv[j];
                const int kk = h * 32 + i * 8 + j * 2;
                const int kglob = kc * 64 + kk;
                const float w0 = fmaf((float)(u & 15), s, o)
                                 * __ldg(inv + kglob);
                const float w1 = fmaf((float)((u >> 4) & 15), s, o)
                                 * __ldg(inv + kglob + 1);
                st[b_u32(r, kk)] = pack_h2(w0, w1);
            }
        }
        __syncthreads();
        uint4* dst = (uint4*)(g_w + (size_t)tile * TILE_U32);
        const uint4* ss = (const uint4*)st;
#pragma unroll
        for (int i = 0; i < 4; ++i)
            dst[i * 256 + tid] = ss[i * 256 + tid];
    } else {
        const int tile = blockIdx.x - W_TILES;   // mT * NKC + kc
        const int mT = tile / NKC, kc = tile % NKC;
        const int m = mT * 128 + r;
        const float4* src =
            (const float4*)(x + (size_t)m * IN_DIM + kc * 64 + h * 32);

#pragma unroll
        for (int i = 0; i < 8; ++i) {
            const float4 v = src[i];
            const int kk = h * 32 + i * 4;
            st[a_u32(r, kk)]     = pack_h2(v.x, v.y);
            st[a_u32(r, kk + 2)] = pack_h2(v.z, v.w);
        }
        __syncthreads();
        uint4* dst = (uint4*)(g_x + (size_t)tile * TILE_U32);
        const uint4* ss = (const uint4*)st;
#pragma unroll
        for (int i = 0; i < 4; ++i)
            dst[i * 256 + tid] = ss[i * 256 + tid];
    }
}

// ============================================================================
// Main GEMM: 256x128 per CTA, 512 threads (16 warps), warp tile 64x32.
// Stage layout: [A0 tile][A1 tile][B tile], 48KB per stage, 3 stages.
// ============================================================================
#define MMA_F16(c, a, b0v, b1v)                                                \
    asm volatile("mma.sync.aligned.m16n8k16.row.col.f32.f16.f16.f32 "          \
        "{%0,%1,%2,%3}, {%4,%5,%6,%7}, {%8,%9}, {%0,%1,%2,%3};"                \
        : "+f"((c)[0]), "+f"((c)[1]), "+f"((c)[2]), "+f"((c)[3])               \
        : "r"((a).x), "r"((a).y), "r"((a).z), "r"((a).w),                      \
          "r"(b0v), "r"(b1v))

#define CP_ASYNC16(dst, src)                                                   \
    asm volatile("cp.async.cg.shared.global [%0], [%1], 16;"                   \
                 :: "r"(dst), "l"(src) : "memory")
#define CP_COMMIT()  asm volatile("cp.async.commit_group;" ::: "memory")
#define CP_WAIT1()   asm volatile("cp.async.wait_group 1;" ::: "memory")

__global__ __launch_bounds__(512, 1)
void awq_mma_gemm(const float* __restrict__ bias, float* __restrict__ out) {
    extern __shared__ uint32_t sm[];
    const int tid  = threadIdx.x;
    const int wid  = tid >> 5;
    const int lane = tid & 31;
    const int wn   = wid & 3;       // n 32-quarter
    const int wm2  = wid >> 2;      // m 64-quarter of 256 (0..3)
    const int tA   = wm2 >> 1;      // which 128-row A tile
    const int wm   = wm2 & 1;       // m64-half within that tile

    // supertile raster: grid(128, 22); x: 8 nT x 16 mT2 inside a supertile
    const int sc  = blockIdx.y % 11;      // supercolumn (8 nT each)
    const int smr = blockIdx.y / 11;      // superrow (16 mT2 each)
    const int nT  = sc * 8 + (blockIdx.x & 7);
    const int mT2 = smr * 16 + (blockIdx.x >> 3);
    if (nT >= NT_TILES) return;

    const uint32_t* a0Src = g_x + (size_t)(mT2 * 2)     * NKC * TILE_U32;
    const uint32_t* a1Src = g_x + (size_t)(mT2 * 2 + 1) * NKC * TILE_U32;
    const uint32_t* bSrc  = g_w + (size_t)nT * NKC * TILE_U32;
    const uint32_t sb = smem_u32(sm);

    float acc[4][4][4];
#pragma unroll
    for (int b = 0; b < 4; ++b)
#pragma unroll
        for (int nb = 0; nb < 4; ++nb)
#pragma unroll
            for (int i = 0; i < 4; ++i) acc[b][nb][i] = 0.0f;

    // ---- pipeline prologue: load chunks 0..STAGES-2 ----
#pragma unroll
    for (int s = 0; s < STAGES - 1; ++s) {
        const uint32_t dst = sb + s * STAGE_U32 * 4;
#pragma unroll
        for (int i = 0; i < 6; ++i) {
            const int f = i * 512 + tid;        // uint4 index, 0..3071
            const uint32_t* src =
                (f < 1024) ? (a0Src + (size_t)s * TILE_U32 + f * 4)
              : (f < 2048) ? (a1Src + (size_t)s * TILE_U32 + (f - 1024) * 4)
                           : (bSrc  + (size_t)s * TILE_U32 + (f - 2048) * 4);
            CP_ASYNC16(dst + f * 16, src);
        }
        CP_COMMIT();
    }

    int stage = 0, pf_stage = STAGES - 1;
#pragma unroll 1
    for (int kc = 0; kc < NKC; ++kc) {
        CP_WAIT1();              // chunk kc resident
        __syncthreads();         // and everyone done with stage being refilled

        // prefetch chunk kc+STAGES-1
        if (kc + STAGES - 1 < NKC) {
            const int pc = kc + STAGES - 1;
            const uint32_t dst = sb + pf_stage * STAGE_U32 * 4;
#pragma unroll
            for (int i = 0; i < 6; ++i) {
                const int f = i * 512 + tid;
                const uint32_t* src =
                    (f < 1024) ? (a0Src + (size_t)pc * TILE_U32 + f * 4)
                  : (f < 2048) ? (a1Src + (size_t)pc * TILE_U32 + (f - 1024) * 4)
                               : (bSrc  + (size_t)pc * TILE_U32 + (f - 2048) * 4);
                CP_ASYNC16(dst + f * 16, src);
            }
        }
        CP_COMMIT();
        if (++pf_stage == STAGES) pf_stage = 0;

        // ---- compute chunk kc (k=64 = 4 k16-steps) ----
        const uint32_t* As = sm + stage * STAGE_U32 + tA * TILE_U32;
        const uint32_t* Bs = sm + stage * STAGE_U32 + 2 * TILE_U32;

#pragma unroll
        for (int ks = 0; ks < 4; ++ks) {
            uint4 Af[4], Bf[2];
#pragma unroll
            for (int b = 0; b < 4; ++b)
                Af[b] = *(const uint4*)
                    (As + ((wm * 16 + ks * 4 + b) * 32 + lane) * 4);
#pragma unroll
            for (int p = 0; p < 2; ++p)
                Bf[p] = *(const uint4*)
                    (Bs + ((((wn * 4 + ks) * 2 + p) * 32) + lane) * 4);

#pragma unroll
            for (int b = 0; b < 4; ++b) {
                const uint4 a = Af[b];
#pragma unroll
                for (int nb = 0; nb < 4; ++nb) {
                    const uint4 bf = Bf[nb >> 1];
                    const uint32_t b0v = (nb & 1) ? bf.z : bf.x;
                    const uint32_t b1v = (nb & 1) ? bf.w : bf.y;
                    MMA_F16(acc[b][nb], a, b0v, b1v);
                }
            }
        }
        if (++stage == STAGES) stage = 0;
    }

    // ---- epilogue: bias + store ----
    const int gid = lane >> 2, tig = lane & 3;
    const int m0 = mT2 * 256 + wm2 * 64;
    const int n0 = nT * 128 + wn * 32;
#pragma unroll
    for (int nb = 0; nb < 4; ++nb) {
        const int n = n0 + nb * 8 + tig * 2;
        const float2 bv = *(const float2*)(bias + n);
#pragma unroll
        for (int b = 0; b < 4; ++b) {
            const int mA = m0 + b * 16 + gid;
            float2 v0, v1;
            v0.x = acc[b][nb][0] + bv.x;
            v0.y = acc[b][nb][1] + bv.y;
            v1.x = acc[b][nb][2] + bv.x;
            v1.y = acc[b][nb][3] + bv.y;
            *(float2*)(out + (size_t)mA * OUT_DIM + n) = v0;
            *(float2*)(out + (size_t)(mA + 8) * OUT_DIM + n) = v1;
        }
    }
}

// ============================================================================
extern "C" void kernel_launch(void* const* d_in, const int* in_sizes, int n_in,
                              void* d_out, int out_size) {
    const float* x         = (const float*)d_in[0];
    const int*   packed    = (const int*)  d_in[1];
    const float* scales    = (const float*)d_in[2];
    const float* offsets   = (const float*)d_in[3];
    const float* inv_scale = (const float*)d_in[4];
    const float* bias      = (const float*)d_in[5];
    float*       out       = (float*)d_out;

    static bool attr_set = false;
    if (!attr_set) {
        cudaFuncSetAttribute(awq_mma_gemm,
                             cudaFuncAttributeMaxDynamicSharedMemorySize,
                             SMEM_BYTES);
        attr_set = true;
    }

    prep_kernel<<<W_TILES + X_TILES, 256>>>(packed, scales, offsets,
                                            inv_scale, x);

    dim3 grid(128, 22);   // 8 nT x 16 mT2 supertiles; 2 superrows x 11 supercols
    awq_mma_gemm<<<grid, 512, SMEM_BYTES>>>(bias, out);
}

// round 9
// speedup vs baseline: 1.0270x; 1.0270x over previous
#include <cuda_runtime.h>
#include <cuda_fp16.h>
#include <cstdint>

// ============================================================================
// AWQ int4 linear via fp16 mma.sync (m16n8k16, fp32 accumulate):
//   (1) merged prepass: dequant W -> 256-wide fp16 fragment tiles,
//       round x -> 128-wide fp16 fragment tiles
//   (2) GEMM: 128x256 CTA tiles, 256 thr (8 warps, warp tile 64x64),
//       k-chunk 64, 4-stage cp.async pipeline, 1 CTA/SM.
// Warp 64x64 doubles the MMA:LDS ratio (32 MMA per 8 LDS.128) and halves
// cross-warp smem re-reads: crossbar load drops 75% -> ~38% of chunk time.
// out[m][n] = sum_k x[m][k]*W[n][k] + bias[n]
// W[n][k] = (q[n][k]*scales[g]+offsets[g])*inv_scale[k], g = n*32 + k/128
// M=8192, N=11008, K=4096.
// ============================================================================

#define IN_DIM   4096
#define OUT_DIM  11008
#define M_DIM    8192
#define BKC      64                    // k per pipeline stage
#define NKC      (IN_DIM / BKC)        // 64 k-chunks
#define STAGES   4
#define A_U32    4096                  // 128x64 fp16 A tile (16KB)
#define B_U32    8192                  // 256x64 fp16 B tile (32KB)
#define STAGE_U32 (A_U32 + B_U32)      // 48KB
#define SMEM_BYTES (STAGES * STAGE_U32 * 4)   // 196608 (192KB)
#define MT_TILES  (M_DIM / 128)        // 64
#define NT2_TILES (OUT_DIM / 256)      // 43
#define W_BLOCKS  ((OUT_DIM / 128) * NKC)   // 5504 (one per 128-row half)
#define X_BLOCKS  (MT_TILES * NKC)          // 4096

// Pre-tiled fp16 operands in fragment order (static scratch; no allocs).
__device__ uint32_t g_w[(size_t)NT2_TILES * NKC * B_U32];   // 90 MB
__device__ uint32_t g_x[(size_t)MT_TILES  * NKC * A_U32];   // 67 MB

__device__ __forceinline__ uint32_t smem_u32(const void* p) {
    uint32_t a;
    asm("{ .reg .u64 t; cvta.to.shared.u64 t, %1; cvt.u32.u64 %0, t; }"
        : "=r"(a) : "l"(p));
    return a;
}

// ---- A tile (128x64): vec v = wm*16 + ks*4 + b ----
__device__ __forceinline__ int a_u32(int mm, int kk) {
    const int wm = mm >> 6, b = (mm >> 4) & 3, row = mm & 15;
    const int gid = row & 7, hi = row >> 3;
    const int ks = kk >> 4, kk16 = kk & 15;
    const int colhi = (kk16 >> 3) & 1, tig = (kk16 >> 1) & 3;
    const int v = wm * 16 + ks * 4 + b;
    return (v * 32 + gid * 4 + tig) * 4 + hi + 2 * colhi;
}
// ---- B half-tile local layout (128 rows of a 256-row tile):
//      vec = wl*16 + ks*4 + p, wl = local n64-half (0..1), p = nb pair ----
__device__ __forceinline__ int b_loc(int nn, int kk) {
    const int wl = nn >> 6, nb = (nn >> 3) & 7, gid = nn & 7;
    const int ks = kk >> 4, kk16 = kk & 15;
    const int khi = (kk16 >> 3) & 1, tig = (kk16 >> 1) & 3;
    return ((wl * 16 + ks * 4 + (nb >> 1)) * 32 + gid * 4 + tig) * 4
           + (nb & 1) * 2 + khi;
}

__device__ __forceinline__ uint32_t pack_h2(float lo, float hi) {
    __half2 h = __floats2half2_rn(lo, hi);
    return *(uint32_t*)&h;
}

// ============================================================================
// Merged prepass. W blocks: one 128-row half of a 256x64 B tile each.
// ============================================================================
__global__ __launch_bounds__(256)
void prep_kernel(const int* __restrict__ packed,
                 const float* __restrict__ scales,
                 const float* __restrict__ offsets,
                 const float* __restrict__ inv,
                 const float* __restrict__ x) {
    __shared__ uint32_t st[A_U32];         // 16KB staging (both paths)
    const int tid = threadIdx.x;
    const int r = tid >> 1, h = tid & 1;   // row 0..127, k-half 0..1

    if (blockIdx.x < W_BLOCKS) {
        const int blk = blockIdx.x;        // n128 * NKC + kc
        const int n128 = blk / NKC, kc = blk % NKC;
        const int nT2 = n128 >> 1, half = n128 & 1;
        const int n = n128 * 128 + r;
        const int g = (n << 5) + (kc >> 1);
        const float s = __ldg(scales + g);
        const float o = __ldg(offsets + g);
        const int kbase = kc * 64 + h * 32;
        const int* src = packed + (size_t)n * 2048 + (kbase >> 1);

#pragma unroll
        for (int i = 0; i < 4; ++i) {
            const int4 u4 = *(const int4*)(src + i * 4);
            const int uv[4] = {u4.x, u4.y, u4.z, u4.w};
#pragma unroll
            for (int j = 0; j < 4; ++j) {
                const int u = uv[j];
                const int kk = h * 32 + i * 8 + j * 2;
                const int kglob = kc * 64 + kk;
                const float w0 = fmaf((float)(u & 15), s, o)
                                 * __ldg(inv + kglob);
                const float w1 = fmaf((float)((u >> 4) & 15), s, o)
                                 * __ldg(inv + kglob + 1);
                st[b_loc(r, kk)] = pack_h2(w0, w1);
            }
        }
        __syncthreads();
        uint4* dst = (uint4*)(g_w + ((size_t)(nT2 * NKC + kc)) * B_U32
                              + half * A_U32);
        const uint4* ss = (const uint4*)st;
#pragma unroll
        for (int i = 0; i < 4; ++i)
            dst[i * 256 + tid] = ss[i * 256 + tid];
    } else {
        const int blk = blockIdx.x - W_BLOCKS;   // mT * NKC + kc
        const int mT = blk / NKC, kc = blk % NKC;
        const int m = mT * 128 + r;
        const float4* src =
            (const float4*)(x + (size_t)m * IN_DIM + kc * 64 + h * 32);

#pragma unroll
        for (int i = 0; i < 8; ++i) {
            const float4 v = src[i];
            const int kk = h * 32 + i * 4;
            st[a_u32(r, kk)]     = pack_h2(v.x, v.y);
            st[a_u32(r, kk + 2)] = pack_h2(v.z, v.w);
        }
        __syncthreads();
        uint4* dst = (uint4*)(g_x + (size_t)blk * A_U32);
        const uint4* ss = (const uint4*)st;
#pragma unroll
        for (int i = 0; i < 4; ++i)
            dst[i * 256 + tid] = ss[i * 256 + tid];
    }
}

// ============================================================================
// Main GEMM: 128x256 per CTA, 256 threads, warp tile 64x64 (2 wm x 4 wn).
// Stage layout: [A 16KB][B 32KB], 4 stages (192KB).
// ============================================================================
#define MMA_F16(c, a, b0v, b1v)                                                \
    asm volatile("mma.sync.aligned.m16n8k16.row.col.f32.f16.f16.f32 "          \
        "{%0,%1,%2,%3}, {%4,%5,%6,%7}, {%8,%9}, {%0,%1,%2,%3};"                \
        : "+f"((c)[0]), "+f"((c)[1]), "+f"((c)[2]), "+f"((c)[3])               \
        : "r"((a).x), "r"((a).y), "r"((a).z), "r"((a).w),                      \
          "r"(b0v), "r"(b1v))

#define CP_ASYNC16(dst, src)                                                   \
    asm volatile("cp.async.cg.shared.global [%0], [%1], 16;"                   \
                 :: "r"(dst), "l"(src) : "memory")
#define CP_COMMIT()  asm volatile("cp.async.commit_group;" ::: "memory")
#define CP_WAIT2()   asm volatile("cp.async.wait_group 2;" ::: "memory")

__global__ __launch_bounds__(256, 1)
void awq_mma_gemm(const float* __restrict__ bias, float* __restrict__ out) {
    extern __shared__ uint32_t sm[];
    const int tid  = threadIdx.x;
    const int wid  = tid >> 5;
    const int lane = tid & 31;
    const int wm   = wid >> 2;      // m 64-half (0..1)
    const int wn   = wid & 3;       // n 64-quarter (0..3)

    // raster: grid(128, 22); x: 4 nT2 x 32 mT; y: 11 supercols x 2 superrows
    const int sc  = blockIdx.y % 11;
    const int smr = blockIdx.y / 11;
    const int nT2 = sc * 4 + (blockIdx.x & 3);
    const int mT  = smr * 32 + (blockIdx.x >> 2);
    if (nT2 >= NT2_TILES) return;

    const uint32_t* aSrc = g_x + (size_t)mT * NKC * A_U32;
    const uint32_t* bSrc = g_w + (size_t)nT2 * NKC * B_U32;
    const uint32_t sb = smem_u32(sm);

    float acc[4][8][4];
#pragma unroll
    for (int b = 0; b < 4; ++b)
#pragma unroll
        for (int nb = 0; nb < 8; ++nb)
#pragma unroll
            for (int i = 0; i < 4; ++i) acc[b][nb][i] = 0.0f;

    // ---- pipeline prologue: load chunks 0..STAGES-2 ----
#pragma unroll
    for (int s = 0; s < STAGES - 1; ++s) {
        const uint32_t dst = sb + s * STAGE_U32 * 4;
#pragma unroll
        for (int i = 0; i < 12; ++i) {
            const int f = i * 256 + tid;        // uint4 index, 0..3071
            const uint32_t* src = (f < 1024)
                ? (aSrc + (size_t)s * A_U32 + f * 4)
                : (bSrc + (size_t)s * B_U32 + (f - 1024) * 4);
            CP_ASYNC16(dst + f * 16, src);
        }
        CP_COMMIT();
    }

    int stage = 0, pf_stage = STAGES - 1;
#pragma unroll 1
    for (int kc = 0; kc < NKC; ++kc) {
        CP_WAIT2();              // chunk kc resident
        __syncthreads();         // everyone done with stage being refilled

        if (kc + STAGES - 1 < NKC) {
            const int pc = kc + STAGES - 1;
            const uint32_t dst = sb + pf_stage * STAGE_U32 * 4;
#pragma unroll
            for (int i = 0; i < 12; ++i) {
                const int f = i * 256 + tid;
                const uint32_t* src = (f < 1024)
                    ? (aSrc + (size_t)pc * A_U32 + f * 4)
                    : (bSrc + (size_t)pc * B_U32 + (f - 1024) * 4);
                CP_ASYNC16(dst + f * 16, src);
            }
        }
        CP_COMMIT();
        if (++pf_stage == STAGES) pf_stage = 0;

        // ---- compute chunk kc (k=64 = 4 k16-steps) ----
        const uint32_t* As = sm + stage * STAGE_U32;
        const uint32_t* Bs = As + A_U32;

#pragma unroll
        for (int ks = 0; ks < 4; ++ks) {
            uint4 Af[4], Bf[4];
#pragma unroll
            for (int b = 0; b < 4; ++b)
                Af[b] = *(const uint4*)
                    (As + ((wm * 16 + ks * 4 + b) * 32 + lane) * 4);
#pragma unroll
            for (int p = 0; p < 4; ++p)
                Bf[p] = *(const uint4*)
                    (Bs + ((wn * 16 + ks * 4 + p) * 32 + lane) * 4);

#pragma unroll
            for (int b = 0; b < 4; ++b) {
                const uint4 a = Af[b];
#pragma unroll
                for (int nb = 0; nb < 8; ++nb) {
                    const uint4 bf = Bf[nb >> 1];
                    const uint32_t b0v = (nb & 1) ? bf.z : bf.x;
                    const uint32_t b1v = (nb & 1) ? bf.w : bf.y;
                    MMA_F16(acc[b][nb], a, b0v, b1v);
                }
            }
        }
        if (++stage == STAGES) stage = 0;
    }

    // ---- epilogue: bias + store ----
    const int gid = lane >> 2, tig = lane & 3;
    const int m0 = mT * 128 + wm * 64;
    const int n0 = nT2 * 256 + wn * 64;
#pragma unroll
    for (int nb = 0; nb < 8; ++nb) {
        const int n = n0 + nb * 8 + tig * 2;
        const float2 bv = *(const float2*)(bias + n);
#pragma unroll
        for (int b = 0; b < 4; ++b) {
            const int mA = m0 + b * 16 + gid;
            float2 v0, v1;
            v0.x = acc[b][nb][0] + bv.x;
            v0.y = acc[b][nb][1] + bv.y;
            v1.x = acc[b][nb][2] + bv.x;
            v1.y = acc[b][nb][3] + bv.y;
            *(float2*)(out + (size_t)mA * OUT_DIM + n) = v0;
            *(float2*)(out + (size_t)(mA + 8) * OUT_DIM + n) = v1;
        }
    }
}

// ============================================================================
extern "C" void kernel_launch(void* const* d_in, const int* in_sizes, int n_in,
                              void* d_out, int out_size) {
    const float* x         = (const float*)d_in[0];
    const int*   packed    = (const int*)  d_in[1];
    const float* scales    = (const float*)d_in[2];
    const float* offsets   = (const float*)d_in[3];
    const float* inv_scale = (const float*)d_in[4];
    const float* bias      = (const float*)d_in[5];
    float*       out       = (float*)d_out;

    static bool attr_set = false;
    if (!attr_set) {
        cudaFuncSetAttribute(awq_mma_gemm,
                             cudaFuncAttributeMaxDynamicSharedMemorySize,
                             SMEM_BYTES);
        attr_set = true;
    }

    prep_kernel<<<W_BLOCKS + X_BLOCKS, 256>>>(packed, scales, offsets,
                                              inv_scale, x);

    dim3 grid(128, 22);   // 4 nT2 x 32 mT supertiles; 2 superrows x 11 supercols
    awq_mma_gemm<<<grid, 256, SMEM_BYTES>>>(bias, out);
}

// round 10
// speedup vs baseline: 1.1554x; 1.1250x over previous
#include <cuda_runtime.h>
#include <cuda_fp16.h>
#include <cstdint>

// ============================================================================
// AWQ int4 linear via fp16 mma.sync (m16n8k16, fp32 accumulate):
//   (1) merged prepass: dequant W + round x -> fp16 fragment-order tiles
//   (2) GEMM: 128x128 CTA tiles, 8 warps (warp 64x32), k-chunk 64, 3-stage
//       cp.async pipeline with PER-STAGE MBARRIERS (no bar.sync in mainloop):
//       warps drift up to 3 chunks, keeping the HMMA pipe fed across chunk
//       boundaries. 2 CTAs/SM.
// out[m][n] = sum_k x[m][k]*W[n][k] + bias[n]
// W[n][k] = (q[n][k]*scales[g]+offsets[g])*inv_scale[k], g = n*32 + k/128
// M=8192, N=11008, K=4096.
// ============================================================================

#define IN_DIM   4096
#define OUT_DIM  11008
#define M_DIM    8192
#define BKC      64                    // k per pipeline stage
#define NKC      (IN_DIM / BKC)        // 64 k-chunks
#define STAGES   3
#define TILE_U32 4096                  // one 128x64 fp16 operand tile (16KB)
#define STAGE_U32 (2 * TILE_U32)       // A tile then B tile (32KB)
#define SMEM_BYTES (STAGES * STAGE_U32 * 4 + 64)   // 96KB + barriers
#define MT_TILES  (M_DIM / 128)        // 64
#define NT_TILES  (OUT_DIM / 128)      // 86
#define W_TILES   (NT_TILES * NKC)     // 5504
#define X_TILES   (MT_TILES * NKC)     // 4096

// Pre-tiled fp16 operands in fragment order (static scratch; no allocs).
__device__ uint32_t g_w[(size_t)W_TILES * TILE_U32];   // 90 MB
__device__ uint32_t g_x[(size_t)X_TILES * TILE_U32];   // 67 MB

__device__ __forceinline__ uint32_t smem_u32(const void* p) {
    uint32_t a;
    asm("{ .reg .u64 t; cvta.to.shared.u64 t, %1; cvt.u32.u64 %0, t; }"
        : "=r"(a) : "l"(p));
    return a;
}

// ---- fragment-order u32 offsets within a 4096-u32 (128 x 64 fp16) tile ----
__device__ __forceinline__ int a_u32(int mm, int kk) {
    const int wm = mm >> 6, b = (mm >> 4) & 3, row = mm & 15;
    const int gid = row & 7, hi = row >> 3;
    const int ks = kk >> 4, kk16 = kk & 15;
    const int colhi = (kk16 >> 3) & 1, tig = (kk16 >> 1) & 3;
    const int v = wm * 16 + ks * 4 + b;
    return (v * 32 + gid * 4 + tig) * 4 + hi + 2 * colhi;
}
__device__ __forceinline__ int b_u32(int nn, int kk) {
    const int wn = nn >> 5, nb = (nn >> 3) & 3, gid = nn & 7;
    const int ks = kk >> 4, kk16 = kk & 15;
    const int khi = (kk16 >> 3) & 1, tig = (kk16 >> 1) & 3;
    return ((((wn * 4 + ks) * 2 + (nb >> 1)) * 32) + gid * 4 + tig) * 4
           + (nb & 1) * 2 + khi;
}

__device__ __forceinline__ uint32_t pack_h2(float lo, float hi) {
    __half2 h = __floats2half2_rn(lo, hi);
    return *(uint32_t*)&h;
}

// ---- mbarrier / cp.async primitives ----
#define MBAR_INIT(a, c) \
    asm volatile("mbarrier.init.shared.b64 [%0], %1;" :: "r"(a), "r"(c) : "memory")
#define MBAR_ARRIVE(a) \
    asm volatile("mbarrier.arrive.shared.b64 _, [%0];" :: "r"(a) : "memory")
#define CP_MBAR_ARRIVE(a) \
    asm volatile("cp.async.mbarrier.arrive.noinc.shared.b64 [%0];" \
                 :: "r"(a) : "memory")
#define MBAR_WAIT(a, ph) do {                                                  \
    uint32_t _m = (a), _p = (uint32_t)(ph), _d;                                \
    asm volatile("{\n\t.reg .pred p;\n\t"                                      \
        "mbarrier.try_wait.parity.acquire.cta.shared::cta.b64 p, [%1], %2;\n\t"\
        "selp.b32 %0, 1, 0, p;\n\t}" : "=r"(_d) : "r"(_m), "r"(_p) : "memory");\
    if (!_d) {                                                                 \
        asm volatile("{\n\t.reg .pred P1;\n\t"                                 \
            "W%=:\n\t"                                                         \
            "mbarrier.try_wait.parity.acquire.cta.shared::cta.b64 P1, [%0], %1, 0x989680;\n\t" \
            "@P1 bra.uni D%=;\n\t"                                             \
            "bra.uni W%=;\n\t"                                                 \
            "D%=:\n\t}" :: "r"(_m), "r"(_p) : "memory");                       \
    }                                                                          \
} while (0)

#define CP_ASYNC16(dst, src)                                                   \
    asm volatile("cp.async.cg.shared.global [%0], [%1], 16;"                   \
                 :: "r"(dst), "l"(src) : "memory")

#define MMA_F16(c, a, b0v, b1v)                                                \
    asm volatile("mma.sync.aligned.m16n8k16.row.col.f32.f16.f16.f32 "          \
        "{%0,%1,%2,%3}, {%4,%5,%6,%7}, {%8,%9}, {%0,%1,%2,%3};"                \
        : "+f"((c)[0]), "+f"((c)[1]), "+f"((c)[2]), "+f"((c)[3])               \
        : "r"((a).x), "r"((a).y), "r"((a).z), "r"((a).w),                      \
          "r"(b0v), "r"(b1v))

// ============================================================================
// Merged prepass: blocks [0, W_TILES) dequant W tiles; rest build x tiles.
// ============================================================================
__global__ __launch_bounds__(256)
void prep_kernel(const int* __restrict__ packed,
                 const float* __restrict__ scales,
                 const float* __restrict__ offsets,
                 const float* __restrict__ inv,
                 const float* __restrict__ x) {
    __shared__ uint32_t st[TILE_U32];
    const int tid = threadIdx.x;
    const int r = tid >> 1, h = tid & 1;   // row 0..127, k-half 0..1

    if (blockIdx.x < W_TILES) {
        const int tile = blockIdx.x;       // nT * NKC + kc
        const int nT = tile / NKC, kc = tile % NKC;
        const int n = nT * 128 + r;
        const int g = (n << 5) + (kc >> 1);
        const float s = __ldg(scales + g);
        const float o = __ldg(offsets + g);
        const int kbase = kc * 64 + h * 32;
        const int* src = packed + (size_t)n * 2048 + (kbase >> 1);

#pragma unroll
        for (int i = 0; i < 4; ++i) {
            const int4 u4 = *(const int4*)(src + i * 4);
            const int uv[4] = {u4.x, u4.y, u4.z, u4.w};
#pragma unroll
            for (int j = 0; j < 4; ++j) {
                const int u = uv[j];
                const int kk = h * 32 + i * 8 + j * 2;
                const int kglob = kc * 64 + kk;
                const float w0 = fmaf((float)(u & 15), s, o)
                                 * __ldg(inv + kglob);
                const float w1 = fmaf((float)((u >> 4) & 15), s, o)
                                 * __ldg(inv + kglob + 1);
                st[b_u32(r, kk)] = pack_h2(w0, w1);
            }
        }
        __syncthreads();
        uint4* dst = (uint4*)(g_w + (size_t)tile * TILE_U32);
        const uint4* ss = (const uint4*)st;
#pragma unroll
        for (int i = 0; i < 4; ++i)
            dst[i * 256 + tid] = ss[i * 256 + tid];
    } else {
        const int tile = blockIdx.x - W_TILES;   // mT * NKC + kc
        const int mT = tile / NKC, kc = tile % NKC;
        const int m = mT * 128 + r;
        const float4* src =
            (const float4*)(x + (size_t)m * IN_DIM + kc * 64 + h * 32);

#pragma unroll
        for (int i = 0; i < 8; ++i) {
            const float4 v = src[i];
            const int kk = h * 32 + i * 4;
            st[a_u32(r, kk)]     = pack_h2(v.x, v.y);
            st[a_u32(r, kk + 2)] = pack_h2(v.z, v.w);
        }
        __syncthreads();
        uint4* dst = (uint4*)(g_x + (size_t)tile * TILE_U32);
        const uint4* ss = (const uint4*)st;
#pragma unroll
        for (int i = 0; i < 4; ++i)
            dst[i * 256 + tid] = ss[i * 256 + tid];
    }
}

// ============================================================================
// Main GEMM: 128x128 per CTA, 256 threads, warp 64x32, mbarrier pipeline.
// smem: 3 stages x [A 16KB | B 16KB], then full[3] @ +0, empty[3] @ +24.
// ============================================================================
__global__ __launch_bounds__(256, 2)
void awq_mma_gemm(const float* __restrict__ bias, float* __restrict__ out) {
    extern __shared__ uint32_t sm[];
    const int tid  = threadIdx.x;
    const int wid  = tid >> 5;
    const int lane = tid & 31;
    const int wm   = wid >> 2;      // m 64-half
    const int wn   = wid & 3;       // n 32-quarter

    // supertile raster: grid(256, 22); x: 8 nT x 32 mT inside a supertile
    const int sc  = blockIdx.y % 11;
    const int smr = blockIdx.y / 11;
    const int nT  = sc * 8 + (blockIdx.x & 7);
    const int mT  = smr * 32 + (blockIdx.x >> 3);
    if (nT >= NT_TILES) return;

    const uint32_t* aSrc = g_x + (size_t)mT * NKC * TILE_U32;
    const uint32_t* bSrc = g_w + (size_t)nT * NKC * TILE_U32;
    const uint32_t sb  = smem_u32(sm);
    const uint32_t bar = sb + STAGES * STAGE_U32 * 4;   // full[s]=+8s, empty=+24+8s

    if (tid == 0) {
#pragma unroll
        for (int s = 0; s < STAGES; ++s) {
            MBAR_INIT(bar + 8 * s, 256);       // full: one cp-arrive per thread
            MBAR_INIT(bar + 24 + 8 * s, 8);    // empty: one arrive per warp
        }
    }
    __syncthreads();

    float acc[4][4][4];
#pragma unroll
    for (int b = 0; b < 4; ++b)
#pragma unroll
        for (int nb = 0; nb < 4; ++nb)
#pragma unroll
            for (int i = 0; i < 4; ++i) acc[b][nb][i] = 0.0f;

    // ---- prologue: fill stages 0..STAGES-2 ----
#pragma unroll
    for (int s = 0; s < STAGES - 1; ++s) {
        const uint32_t dst = sb + s * STAGE_U32 * 4;
#pragma unroll
        for (int i = 0; i < 8; ++i) {
            const int f = i * 256 + tid;        // uint4 index, 0..2047
            const uint32_t* src = (f < 1024)
                ? (aSrc + (size_t)s * TILE_U32 + f * 4)
                : (bSrc + (size_t)s * TILE_U32 + (f - 1024) * 4);
            CP_ASYNC16(dst + f * 16, src);
        }
        CP_MBAR_ARRIVE(bar + 8 * s);
    }

    int scur = 0, fpar = 0;        // consumer cursor: stage, full parity
    int ps = STAGES - 1, ep = 1;   // producer cursor: stage, empty parity
#pragma unroll 1
    for (int kc = 0; kc < NKC; ++kc) {
        // ---- producer: fill chunk kc+STAGES-1 into stage ps ----
        const int pc = kc + STAGES - 1;
        if (pc < NKC) {
            if (pc >= STAGES) MBAR_WAIT(bar + 24 + 8 * ps, ep);
            const uint32_t dst = sb + ps * STAGE_U32 * 4;
#pragma unroll
            for (int i = 0; i < 8; ++i) {
                const int f = i * 256 + tid;
                const uint32_t* src = (f < 1024)
                    ? (aSrc + (size_t)pc * TILE_U32 + f * 4)
                    : (bSrc + (size_t)pc * TILE_U32 + (f - 1024) * 4);
                CP_ASYNC16(dst + f * 16, src);
            }
            CP_MBAR_ARRIVE(bar + 8 * ps);
        }
        if (++ps == STAGES) { ps = 0; ep ^= 1; }

        // ---- consumer: wait chunk kc, compute ----
        MBAR_WAIT(bar + 8 * scur, fpar);

        const uint32_t* As = sm + scur * STAGE_U32;
        const uint32_t* Bs = As + TILE_U32;
#pragma unroll
        for (int ks = 0; ks < 4; ++ks) {
            uint4 Af[4], Bf[2];
#pragma unroll
            for (int b = 0; b < 4; ++b)
                Af[b] = *(const uint4*)
                    (As + ((wm * 16 + ks * 4 + b) * 32 + lane) * 4);
#pragma unroll
            for (int p = 0; p < 2; ++p)
                Bf[p] = *(const uint4*)
                    (Bs + ((((wn * 4 + ks) * 2 + p) * 32) + lane) * 4);

#pragma unroll
            for (int b = 0; b < 4; ++b) {
                const uint4 a = Af[b];
#pragma unroll
                for (int nb = 0; nb < 4; ++nb) {
                    const uint4 bf = Bf[nb >> 1];
                    const uint32_t b0v = (nb & 1) ? bf.z : bf.x;
                    const uint32_t b1v = (nb & 1) ? bf.w : bf.y;
                    MMA_F16(acc[b][nb], a, b0v, b1v);
                }
            }
        }
        __syncwarp();
        if (lane == 0) MBAR_ARRIVE(bar + 24 + 8 * scur);
        if (++scur == STAGES) { scur = 0; fpar ^= 1; }
    }

    // ---- epilogue: bias + store ----
    const int gid = lane >> 2, tig = lane & 3;
    const int m0 = mT * 128 + wm * 64;
    const int n0 = nT * 128 + wn * 32;
#pragma unroll
    for (int nb = 0; nb < 4; ++nb) {
        const int n = n0 + nb * 8 + tig * 2;
        const float2 bv = *(const float2*)(bias + n);
#pragma unroll
        for (int b = 0; b < 4; ++b) {
            const int mA = m0 + b * 16 + gid;
            float2 v0, v1;
            v0.x = acc[b][nb][0] + bv.x;
            v0.y = acc[b][nb][1] + bv.y;
            v1.x = acc[b][nb][2] + bv.x;
            v1.y = acc[b][nb][3] + bv.y;
            *(float2*)(out + (size_t)mA * OUT_DIM + n) = v0;
            *(float2*)(out + (size_t)(mA + 8) * OUT_DIM + n) = v1;
        }
    }
}

// ============================================================================
extern "C" void kernel_launch(void* const* d_in, const int* in_sizes, int n_in,
                              void* d_out, int out_size) {
    const float* x         = (const float*)d_in[0];
    const int*   packed    = (const int*)  d_in[1];
    const float* scales    = (const float*)d_in[2];
    const float* offsets   = (const float*)d_in[3];
    const float* inv_scale = (const float*)d_in[4];
    const float* bias      = (const float*)d_in[5];
    float*       out       = (float*)d_out;

    static bool attr_set = false;
    if (!attr_set) {
        cudaFuncSetAttribute(awq_mma_gemm,
                             cudaFuncAttributeMaxDynamicSharedMemorySize,
                             SMEM_BYTES);
        attr_set = true;
    }

    prep_kernel<<<W_TILES + X_TILES, 256>>>(packed, scales, offsets,
                                            inv_scale, x);

    dim3 grid(256, 22);   // 8 nT x 32 mT supertiles; 2 superrows x 11 supercols
    awq_mma_gemm<<<grid, 256, SMEM_BYTES>>>(bias, out);
}

// round 11
// speedup vs baseline: 1.1831x; 1.0240x over previous
#include <cuda_runtime.h>
#include <cuda_fp16.h>
#include <cstdint>

// ============================================================================
// AWQ int4 linear via fp16 mma.sync (m16n8k16, fp32 accumulate):
//   (1) merged prepass: dequant W + round x -> fp16 fragment-order tiles
//   (2) GEMM: 128x128 CTA tiles, 8 warps (warp 64x32), k-chunk 64, 3-stage
//       cp.async pipeline with per-stage mbarriers (no bar.sync in mainloop),
//       producer specialization by half-CTA (threads 0-127: A, 128-255: B),
//       2 CTAs/SM.
// out[m][n] = sum_k x[m][k]*W[n][k] + bias[n]
// W[n][k] = (q[n][k]*scales[g]+offsets[g])*inv_scale[k], g = n*32 + k/128
// M=8192, N=11008, K=4096.
// ============================================================================

#define IN_DIM   4096
#define OUT_DIM  11008
#define M_DIM    8192
#define BKC      64                    // k per pipeline stage
#define NKC      (IN_DIM / BKC)        // 64 k-chunks
#define STAGES   3
#define TILE_U32 4096                  // one 128x64 fp16 operand tile (16KB)
#define STAGE_U32 (2 * TILE_U32)       // A tile then B tile (32KB)
#define STAGE_BYTES (STAGE_U32 * 4)
#define SMEM_BYTES (STAGES * STAGE_BYTES + 64)   // 96KB + barriers
#define MT_TILES  (M_DIM / 128)        // 64
#define NT_TILES  (OUT_DIM / 128)      // 86
#define W_TILES   (NT_TILES * NKC)     // 5504
#define X_TILES   (MT_TILES * NKC)     // 4096

// Pre-tiled fp16 operands in fragment order (static scratch; no allocs).
__device__ uint32_t g_w[(size_t)W_TILES * TILE_U32];   // 90 MB
__device__ uint32_t g_x[(size_t)X_TILES * TILE_U32];   // 67 MB

__device__ __forceinline__ uint32_t smem_u32(const void* p) {
    uint32_t a;
    asm("{ .reg .u64 t; cvta.to.shared.u64 t, %1; cvt.u32.u64 %0, t; }"
        : "=r"(a) : "l"(p));
    return a;
}

// ---- fragment-order u32 offsets within a 4096-u32 (128 x 64 fp16) tile ----
__device__ __forceinline__ int a_u32(int mm, int kk) {
    const int wm = mm >> 6, b = (mm >> 4) & 3, row = mm & 15;
    const int gid = row & 7, hi = row >> 3;
    const int ks = kk >> 4, kk16 = kk & 15;
    const int colhi = (kk16 >> 3) & 1, tig = (kk16 >> 1) & 3;
    const int v = wm * 16 + ks * 4 + b;
    return (v * 32 + gid * 4 + tig) * 4 + hi + 2 * colhi;
}
__device__ __forceinline__ int b_u32(int nn, int kk) {
    const int wn = nn >> 5, nb = (nn >> 3) & 3, gid = nn & 7;
    const int ks = kk >> 4, kk16 = kk & 15;
    const int khi = (kk16 >> 3) & 1, tig = (kk16 >> 1) & 3;
    return ((((wn * 4 + ks) * 2 + (nb >> 1)) * 32) + gid * 4 + tig) * 4
           + (nb & 1) * 2 + khi;
}

__device__ __forceinline__ uint32_t pack_h2(float lo, float hi) {
    __half2 h = __floats2half2_rn(lo, hi);
    return *(uint32_t*)&h;
}

// ---- mbarrier / cp.async primitives ----
#define MBAR_INIT(a, c) \
    asm volatile("mbarrier.init.shared.b64 [%0], %1;" :: "r"(a), "r"(c) : "memory")
#define MBAR_ARRIVE(a) \
    asm volatile("mbarrier.arrive.shared.b64 _, [%0];" :: "r"(a) : "memory")
#define CP_MBAR_ARRIVE(a) \
    asm volatile("cp.async.mbarrier.arrive.noinc.shared.b64 [%0];" \
                 :: "r"(a) : "memory")
#define MBAR_WAIT(a, ph) do {                                                  \
    uint32_t _m = (a), _p = (uint32_t)(ph), _d;                                \
    asm volatile("{\n\t.reg .pred p;\n\t"                                      \
        "mbarrier.try_wait.parity.acquire.cta.shared::cta.b64 p, [%1], %2;\n\t"\
        "selp.b32 %0, 1, 0, p;\n\t}" : "=r"(_d) : "r"(_m), "r"(_p) : "memory");\
    if (!_d) {                                                                 \
        asm volatile("{\n\t.reg .pred P1;\n\t"                                 \
            "W%=:\n\t"                                                         \
            "mbarrier.try_wait.parity.acquire.cta.shared::cta.b64 P1, [%0], %1, 0x989680;\n\t" \
            "@P1 bra.uni D%=;\n\t"                                             \
            "bra.uni W%=;\n\t"                                                 \
            "D%=:\n\t}" :: "r"(_m), "r"(_p) : "memory");                       \
    }                                                                          \
} while (0)

#define CP_ASYNC16(dst, src)                                                   \
    asm volatile("cp.async.cg.shared.global.L2::256B [%0], [%1], 16;"          \
                 :: "r"(dst), "l"(src) : "memory")

#define MMA_F16(c, a, b0v, b1v)                                                \
    asm volatile("mma.sync.aligned.m16n8k16.row.col.f32.f16.f16.f32 "          \
        "{%0,%1,%2,%3}, {%4,%5,%6,%7}, {%8,%9}, {%0,%1,%2,%3};"                \
        : "+f"((c)[0]), "+f"((c)[1]), "+f"((c)[2]), "+f"((c)[3])               \
        : "r"((a).x), "r"((a).y), "r"((a).z), "r"((a).w),                      \
          "r"(b0v), "r"(b1v))

// ============================================================================
// Merged prepass: blocks [0, W_TILES) dequant W tiles; rest build x tiles.
// ============================================================================
__global__ __launch_bounds__(256)
void prep_kernel(const int* __restrict__ packed,
                 const float* __restrict__ scales,
                 const float* __restrict__ offsets,
                 const float* __restrict__ inv,
                 const float* __restrict__ x) {
    __shared__ uint32_t st[TILE_U32];
    const int tid = threadIdx.x;
    const int r = tid >> 1, h = tid & 1;   // row 0..127, k-half 0..1

    if (blockIdx.x < W_TILES) {
        const int tile = blockIdx.x;       // nT * NKC + kc
        const int nT = tile / NKC, kc = tile % NKC;
        const int n = nT * 128 + r;
        const int g = (n << 5) + (kc >> 1);
        const float s = __ldg(scales + g);
        const float o = __ldg(offsets + g);
        const int kbase = kc * 64 + h * 32;
        const int* src = packed + (size_t)n * 2048 + (kbase >> 1);

#pragma unroll
        for (int i = 0; i < 4; ++i) {
            const int4 u4 = *(const int4*)(src + i * 4);
            const int uv[4] = {u4.x, u4.y, u4.z, u4.w};
#pragma unroll
            for (int j = 0; j < 4; ++j) {
                const int u = uv[j];
                const int kk = h * 32 + i * 8 + j * 2;
                const int kglob = kc * 64 + kk;
                const float w0 = fmaf((float)(u & 15), s, o)
                                 * __ldg(inv + kglob);
                const float w1 = fmaf((float)((u >> 4) & 15), s, o)
                                 * __ldg(inv + kglob + 1);
                st[b_u32(r, kk)] = pack_h2(w0, w1);
            }
        }
        __syncthreads();
        uint4* dst = (uint4*)(g_w + (size_t)tile * TILE_U32);
        const uint4* ss = (const uint4*)st;
#pragma unroll
        for (int i = 0; i < 4; ++i)
            dst[i * 256 + tid] = ss[i * 256 + tid];
    } else {
        const int tile = blockIdx.x - W_TILES;   // mT * NKC + kc
        const int mT = tile / NKC, kc = tile % NKC;
        const int m = mT * 128 + r;
        const float4* src =
            (const float4*)(x + (size_t)m * IN_DIM + kc * 64 + h * 32);

#pragma unroll
        for (int i = 0; i < 8; ++i) {
            const float4 v = src[i];
            const int kk = h * 32 + i * 4;
            st[a_u32(r, kk)]     = pack_h2(v.x, v.y);
            st[a_u32(r, kk + 2)] = pack_h2(v.z, v.w);
        }
        __syncthreads();
        uint4* dst = (uint4*)(g_x + (size_t)tile * TILE_U32);
        const uint4* ss = (const uint4*)st;
#pragma unroll
        for (int i = 0; i < 4; ++i)
            dst[i * 256 + tid] = ss[i * 256 + tid];
    }
}

// ============================================================================
// Main GEMM: 128x128 per CTA, 256 threads, warp 64x32, mbarrier pipeline,
// producer specialization by half-CTA. smem: 3 x [A 16KB | B 16KB] + barriers.
// ============================================================================
__global__ __launch_bounds__(256, 2)
void awq_mma_gemm(const float* __restrict__ bias, float* __restrict__ out) {
    extern __shared__ uint32_t sm[];
    const int tid  = threadIdx.x;
    const int wid  = tid >> 5;
    const int lane = tid & 31;
    const int wm   = wid >> 2;      // m 64-half
    const int wn   = wid & 3;       // n 32-quarter

    // supertile raster: grid(256, 22); x: 8 nT x 32 mT inside a supertile
    const int sc  = blockIdx.y % 11;
    const int smr = blockIdx.y / 11;
    const int nT  = sc * 8 + (blockIdx.x & 7);
    const int mT  = smr * 32 + (blockIdx.x >> 3);
    if (nT >= NT_TILES) return;

    const uint32_t* aSrc = g_x + (size_t)mT * NKC * TILE_U32;
    const uint32_t* bSrc = g_w + (size_t)nT * NKC * TILE_U32;
    const uint32_t sb  = smem_u32(sm);
    const uint32_t bar = sb + STAGES * STAGE_BYTES;   // full[s]=+8s, empty=+24+8s

    // producer role (fixed per thread): lower half copies A, upper half B.
    const int   pl      = tid & 127;                 // 0..127 within half
    const bool  isA     = tid < 128;
    const uint32_t* gBase = (isA ? aSrc : bSrc) + pl * 4;   // + chunk*TILE_U32
    const uint32_t dOff = (isA ? pl : 1024 + pl) * 16;      // byte offset in stage

    if (tid == 0) {
#pragma unroll
        for (int s = 0; s < STAGES; ++s) {
            MBAR_INIT(bar + 8 * s, 256);       // full: one cp-arrive per thread
            MBAR_INIT(bar + 24 + 8 * s, 8);    // empty: one arrive per warp
        }
    }
    __syncthreads();

    float acc[4][4][4];
#pragma unroll
    for (int b = 0; b < 4; ++b)
#pragma unroll
        for (int nb = 0; nb < 4; ++nb)
#pragma unroll
            for (int i = 0; i < 4; ++i) acc[b][nb][i] = 0.0f;

    // ---- prologue: fill stages 0..STAGES-2 ----
#pragma unroll
    for (int s = 0; s < STAGES - 1; ++s) {
        const uint32_t dst = sb + s * STAGE_BYTES + dOff;
        const uint32_t* src = gBase + (size_t)s * TILE_U32;
#pragma unroll
        for (int i = 0; i < 8; ++i)
            CP_ASYNC16(dst + i * 2048, src + i * 512);
        CP_MBAR_ARRIVE(bar + 8 * s);
    }

    int scur = 0, fpar = 0;        // consumer cursor: stage, full parity
    int ps = STAGES - 1, ep = 1;   // producer cursor: stage, empty parity
#pragma unroll 1
    for (int kc = 0; kc < NKC; ++kc) {
        // ---- producer: fill chunk kc+STAGES-1 into stage ps ----
        const int pc = kc + STAGES - 1;
        if (pc < NKC) {
            if (pc >= STAGES) MBAR_WAIT(bar + 24 + 8 * ps, ep);
            const uint32_t dst = sb + ps * STAGE_BYTES + dOff;
            const uint32_t* src = gBase + (size_t)pc * TILE_U32;
#pragma unroll
            for (int i = 0; i < 8; ++i)
                CP_ASYNC16(dst + i * 2048, src + i * 512);
            CP_MBAR_ARRIVE(bar + 8 * ps);
        }
        if (++ps == STAGES) { ps = 0; ep ^= 1; }

        // ---- consumer: wait chunk kc, compute ----
        MBAR_WAIT(bar + 8 * scur, fpar);

        const uint32_t* As = sm + scur * STAGE_U32;
        const uint32_t* Bs = As + TILE_U32;
#pragma unroll
        for (int ks = 0; ks < 4; ++ks) {
            uint4 Af[4], Bf[2];
#pragma unroll
            for (int b = 0; b < 4; ++b)
                Af[b] = *(const uint4*)
                    (As + ((wm * 16 + ks * 4 + b) * 32 + lane) * 4);
#pragma unroll
            for (int p = 0; p < 2; ++p)
                Bf[p] = *(const uint4*)
                    (Bs + ((((wn * 4 + ks) * 2 + p) * 32) + lane) * 4);

#pragma unroll
            for (int b = 0; b < 4; ++b) {
                const uint4 a = Af[b];
#pragma unroll
                for (int nb = 0; nb < 4; ++nb) {
                    const uint4 bf = Bf[nb >> 1];
                    const uint32_t b0v = (nb & 1) ? bf.z : bf.x;
                    const uint32_t b1v = (nb & 1) ? bf.w : bf.y;
                    MMA_F16(acc[b][nb], a, b0v, b1v);
                }
            }
        }
        __syncwarp();
        if (lane == 0) MBAR_ARRIVE(bar + 24 + 8 * scur);
        if (++scur == STAGES) { scur = 0; fpar ^= 1; }
    }

    // ---- epilogue: bias + store ----
    const int gid = lane >> 2, tig = lane & 3;
    const int m0 = mT * 128 + wm * 64;
    const int n0 = nT * 128 + wn * 32;
#pragma unroll
    for (int nb = 0; nb < 4; ++nb) {
        const int n = n0 + nb * 8 + tig * 2;
        const float2 bv = *(const float2*)(bias + n);
#pragma unroll
        for (int b = 0; b < 4; ++b) {
            const int mA = m0 + b * 16 + gid;
            float2 v0, v1;
            v0.x = acc[b][nb][0] + bv.x;
            v0.y = acc[b][nb][1] + bv.y;
            v1.x = acc[b][nb][2] + bv.x;
            v1.y = acc[b][nb][3] + bv.y;
            *(float2*)(out + (size_t)mA * OUT_DIM + n) = v0;
            *(float2*)(out + (size_t)(mA + 8) * OUT_DIM + n) = v1;
        }
    }
}

// ============================================================================
extern "C" void kernel_launch(void* const* d_in, const int* in_sizes, int n_in,
                              void* d_out, int out_size) {
    const float* x         = (const float*)d_in[0];
    const int*   packed    = (const int*)  d_in[1];
    const float* scales    = (const float*)d_in[2];
    const float* offsets   = (const float*)d_in[3];
    const float* inv_scale = (const float*)d_in[4];
    const float* bias      = (const float*)d_in[5];
    float*       out       = (float*)d_out;

    static bool attr_set = false;
    if (!attr_set) {
        cudaFuncSetAttribute(awq_mma_gemm,
                             cudaFuncAttributeMaxDynamicSharedMemorySize,
                             SMEM_BYTES);
        attr_set = true;
    }

    prep_kernel<<<W_TILES + X_TILES, 256>>>(packed, scales, offsets,
                                            inv_scale, x);

    dim3 grid(256, 22);   // 8 nT x 32 mT supertiles; 2 superrows x 11 supercols
    awq_mma_gemm<<<grid, 256, SMEM_BYTES>>>(bias, out);
}

// round 12
// speedup vs baseline: 1.1982x; 1.0128x over previous
#include <cuda_runtime.h>
#include <cuda_fp16.h>
#include <cstdint>

// ============================================================================
// AWQ int4 linear via fp16 mma.sync (m16n8k16, fp32 accumulate):
//   (1) merged prepass: DIRECT fragment-order tile construction (no smem
//       staging): each thread computes 4 complete uint4 fragment units and
//       writes them with coalesced STG.128. Kills the 8-way STS conflicts.
//   (2) GEMM: 128x128 CTA tiles, 8 warps (warp 64x32), k-chunk 64, 3-stage
//       cp.async pipeline with per-stage mbarriers, producer specialization
//       by half-CTA, 2 CTAs/SM.  (unchanged from R11 — 83.3% tensor)
// out[m][n] = sum_k x[m][k]*W[n][k] + bias[n]
// W[n][k] = (q[n][k]*scales[g]+offsets[g])*inv_scale[k], g = n*32 + k/128
// M=8192, N=11008, K=4096.
// ============================================================================

#define IN_DIM   4096
#define OUT_DIM  11008
#define M_DIM    8192
#define BKC      64                    // k per pipeline stage
#define NKC      (IN_DIM / BKC)        // 64 k-chunks
#define STAGES   3
#define TILE_U32 4096                  // one 128x64 fp16 operand tile (16KB)
#define STAGE_U32 (2 * TILE_U32)       // A tile then B tile (32KB)
#define STAGE_BYTES (STAGE_U32 * 4)
#define SMEM_BYTES (STAGES * STAGE_BYTES + 64)   // 96KB + barriers
#define MT_TILES  (M_DIM / 128)        // 64
#define NT_TILES  (OUT_DIM / 128)      // 86
#define W_TILES   (NT_TILES * NKC)     // 5504
#define X_TILES   (MT_TILES * NKC)     // 4096

// Pre-tiled fp16 operands in fragment order (static scratch; no allocs).
__device__ uint32_t g_w[(size_t)W_TILES * TILE_U32];   // 90 MB
__device__ uint32_t g_x[(size_t)X_TILES * TILE_U32];   // 67 MB

__device__ __forceinline__ uint32_t smem_u32(const void* p) {
    uint32_t a;
    asm("{ .reg .u64 t; cvta.to.shared.u64 t, %1; cvt.u32.u64 %0, t; }"
        : "=r"(a) : "l"(p));
    return a;
}

__device__ __forceinline__ uint32_t pack_h2(float lo, float hi) {
    __half2 h = __floats2half2_rn(lo, hi);   // .x = lo half
    return *(uint32_t*)&h;
}

// ---- mbarrier / cp.async primitives ----
#define MBAR_INIT(a, c) \
    asm volatile("mbarrier.init.shared.b64 [%0], %1;" :: "r"(a), "r"(c) : "memory")
#define MBAR_ARRIVE(a) \
    asm volatile("mbarrier.arrive.shared.b64 _, [%0];" :: "r"(a) : "memory")
#define CP_MBAR_ARRIVE(a) \
    asm volatile("cp.async.mbarrier.arrive.noinc.shared.b64 [%0];" \
                 :: "r"(a) : "memory")
#define MBAR_WAIT(a, ph) do {                                                  \
    uint32_t _m = (a), _p = (uint32_t)(ph), _d;                                \
    asm volatile("{\n\t.reg .pred p;\n\t"                                      \
        "mbarrier.try_wait.parity.acquire.cta.shared::cta.b64 p, [%1], %2;\n\t"\
        "selp.b32 %0, 1, 0, p;\n\t}" : "=r"(_d) : "r"(_m), "r"(_p) : "memory");\
    if (!_d) {                                                                 \
        asm volatile("{\n\t.reg .pred P1;\n\t"                                 \
            "W%=:\n\t"                                                         \
            "mbarrier.try_wait.parity.acquire.cta.shared::cta.b64 P1, [%0], %1, 0x989680;\n\t" \
            "@P1 bra.uni D%=;\n\t"                                             \
            "bra.uni W%=;\n\t"                                                 \
            "D%=:\n\t}" :: "r"(_m), "r"(_p) : "memory");                       \
    }                                                                          \
} while (0)

#define CP_ASYNC16(dst, src)                                                   \
    asm volatile("cp.async.cg.shared.global.L2::256B [%0], [%1], 16;"          \
                 :: "r"(dst), "l"(src) : "memory")

#define MMA_F16(c, a, b0v, b1v)                                                \
    asm volatile("mma.sync.aligned.m16n8k16.row.col.f32.f16.f16.f32 "          \
        "{%0,%1,%2,%3}, {%4,%5,%6,%7}, {%8,%9}, {%0,%1,%2,%3};"                \
        : "+f"((c)[0]), "+f"((c)[1]), "+f"((c)[2]), "+f"((c)[3])               \
        : "r"((a).x), "r"((a).y), "r"((a).z), "r"((a).w),                      \
          "r"(b0v), "r"(b1v))

// ============================================================================
// Merged prepass, direct construction.
// B tile uint4 u (0..1023): vec=u>>5, lane=u&31; wn=vec>>3, ks=(vec>>1)&3,
//   p=vec&1, gid=lane>>2, tig=lane&3. Rows nn0=wn*32+p*16+gid, nn0+8;
//   cols kk0=ks*16+tig*2, kk0+8. Slots: [n0k0, n0k1, n1k0, n1k1].
// A tile uint4 u: wm=vec>>4, ks=(vec>>2)&3, b=vec&3. Rows mm0=wm*64+b*16+gid,
//   mm0+8; cols kk0, kk0+8. Slots: [m0k0, m1k0, m0k1, m1k1].
// ============================================================================
__global__ __launch_bounds__(256)
void prep_kernel(const int* __restrict__ packed,
                 const float* __restrict__ scales,
                 const float* __restrict__ offsets,
                 const float* __restrict__ inv,
                 const float* __restrict__ x) {
    const int tid = threadIdx.x;

    if (blockIdx.x < W_TILES) {
        const int tile = blockIdx.x;           // nT * NKC + kc
        const int nT = tile / NKC, kc = tile % NKC;
        const int kb = kc * 64;
        uint4* dst = (uint4*)(g_w + (size_t)tile * TILE_U32);
#pragma unroll
        for (int q = 0; q < 4; ++q) {
            const int u = q * 256 + tid;
            const int vec = u >> 5, lane = u & 31;
            const int wn = vec >> 3, ks = (vec >> 1) & 3, p = vec & 1;
            const int gid = lane >> 2, tig = lane & 3;
            const int kk0 = ks * 16 + tig * 2;
            const int kk1 = kk0 + 8;
            const int n0 = nT * 128 + wn * 32 + p * 16 + gid;
            const int n1 = n0 + 8;
            const int gr0 = (n0 << 5) + (kc >> 1);
            const int gr1 = (n1 << 5) + (kc >> 1);
            const float s0 = __ldg(scales + gr0), o0 = __ldg(offsets + gr0);
            const float s1 = __ldg(scales + gr1), o1 = __ldg(offsets + gr1);
            const int u00 = __ldg(packed + (size_t)n0 * 2048 + ((kb + kk0) >> 1));
            const int u01 = __ldg(packed + (size_t)n0 * 2048 + ((kb + kk1) >> 1));
            const int u10 = __ldg(packed + (size_t)n1 * 2048 + ((kb + kk0) >> 1));
            const int u11 = __ldg(packed + (size_t)n1 * 2048 + ((kb + kk1) >> 1));
            const float2 i0 = *(const float2*)(inv + kb + kk0);
            const float2 i1 = *(const float2*)(inv + kb + kk1);
            uint4 o;
            o.x = pack_h2(fmaf((float)(u00 & 15), s0, o0) * i0.x,
                          fmaf((float)((u00 >> 4) & 15), s0, o0) * i0.y);
            o.y = pack_h2(fmaf((float)(u01 & 15), s0, o0) * i1.x,
                          fmaf((float)((u01 >> 4) & 15), s0, o0) * i1.y);
            o.z = pack_h2(fmaf((float)(u10 & 15), s1, o1) * i0.x,
                          fmaf((float)((u10 >> 4) & 15), s1, o1) * i0.y);
            o.w = pack_h2(fmaf((float)(u11 & 15), s1, o1) * i1.x,
                          fmaf((float)((u11 >> 4) & 15), s1, o1) * i1.y);
            dst[u] = o;
        }
    } else {
        const int tile = blockIdx.x - W_TILES;   // mT * NKC + kc
        const int mT = tile / NKC, kc = tile % NKC;
        const int kb = kc * 64;
        uint4* dst = (uint4*)(g_x + (size_t)tile * TILE_U32);
#pragma unroll
        for (int q = 0; q < 4; ++q) {
            const int u = q * 256 + tid;
            const int vec = u >> 5, lane = u & 31;
            const int wm = vec >> 4, ks = (vec >> 2) & 3, b = vec & 3;
            const int gid = lane >> 2, tig = lane & 3;
            const int kk0 = ks * 16 + tig * 2;
            const int kk1 = kk0 + 8;
            const int m0 = mT * 128 + wm * 64 + b * 16 + gid;
            const int m1 = m0 + 8;
            const float2 x00 = *(const float2*)(x + (size_t)m0 * IN_DIM + kb + kk0);
            const float2 x01 = *(const float2*)(x + (size_t)m0 * IN_DIM + kb + kk1);
            const float2 x10 = *(const float2*)(x + (size_t)m1 * IN_DIM + kb + kk0);
            const float2 x11 = *(const float2*)(x + (size_t)m1 * IN_DIM + kb + kk1);
            uint4 o;
            o.x = pack_h2(x00.x, x00.y);
            o.y = pack_h2(x10.x, x10.y);
            o.z = pack_h2(x01.x, x01.y);
            o.w = pack_h2(x11.x, x11.y);
            dst[u] = o;
        }
    }
}

// ============================================================================
// Main GEMM: 128x128 per CTA, 256 threads, warp 64x32, mbarrier pipeline,
// producer specialization by half-CTA. smem: 3 x [A 16KB | B 16KB] + barriers.
// (unchanged from R11)
// ============================================================================
__global__ __launch_bounds__(256, 2)
void awq_mma_gemm(const float* __restrict__ bias, float* __restrict__ out) {
    extern __shared__ uint32_t sm[];
    const int tid  = threadIdx.x;
    const int wid  = tid >> 5;
    const int lane = tid & 31;
    const int wm   = wid >> 2;      // m 64-half
    const int wn   = wid & 3;       // n 32-quarter

    // supertile raster: grid(256, 22); x: 8 nT x 32 mT inside a supertile
    const int sc  = blockIdx.y % 11;
    const int smr = blockIdx.y / 11;
    const int nT  = sc * 8 + (blockIdx.x & 7);
    const int mT  = smr * 32 + (blockIdx.x >> 3);
    if (nT >= NT_TILES) return;

    const uint32_t* aSrc = g_x + (size_t)mT * NKC * TILE_U32;
    const uint32_t* bSrc = g_w + (size_t)nT * NKC * TILE_U32;
    const uint32_t sb  = smem_u32(sm);
    const uint32_t bar = sb + STAGES * STAGE_BYTES;   // full[s]=+8s, empty=+24+8s

    // producer role (fixed per thread): lower half copies A, upper half B.
    const int   pl      = tid & 127;                 // 0..127 within half
    const bool  isA     = tid < 128;
    const uint32_t* gBase = (isA ? aSrc : bSrc) + pl * 4;   // + chunk*TILE_U32
    const uint32_t dOff = (isA ? pl : 1024 + pl) * 16;      // byte offset in stage

    if (tid == 0) {
#pragma unroll
        for (int s = 0; s < STAGES; ++s) {
            MBAR_INIT(bar + 8 * s, 256);       // full: one cp-arrive per thread
            MBAR_INIT(bar + 24 + 8 * s, 8);    // empty: one arrive per warp
        }
    }
    __syncthreads();

    float acc[4][4][4];
#pragma unroll
    for (int b = 0; b < 4; ++b)
#pragma unroll
        for (int nb = 0; nb < 4; ++nb)
#pragma unroll
            for (int i = 0; i < 4; ++i) acc[b][nb][i] = 0.0f;

    // ---- prologue: fill stages 0..STAGES-2 ----
#pragma unroll
    for (int s = 0; s < STAGES - 1; ++s) {
        const uint32_t dst = sb + s * STAGE_BYTES + dOff;
        const uint32_t* src = gBase + (size_t)s * TILE_U32;
#pragma unroll
        for (int i = 0; i < 8; ++i)
            CP_ASYNC16(dst + i * 2048, src + i * 512);
        CP_MBAR_ARRIVE(bar + 8 * s);
    }

    int scur = 0, fpar = 0;        // consumer cursor: stage, full parity
    int ps = STAGES - 1, ep = 1;   // producer cursor: stage, empty parity
#pragma unroll 1
    for (int kc = 0; kc < NKC; ++kc) {
        // ---- producer: fill chunk kc+STAGES-1 into stage ps ----
        const int pc = kc + STAGES - 1;
        if (pc < NKC) {
            if (pc >= STAGES) MBAR_WAIT(bar + 24 + 8 * ps, ep);
            const uint32_t dst = sb + ps * STAGE_BYTES + dOff;
            const uint32_t* src = gBase + (size_t)pc * TILE_U32;
#pragma unroll
            for (int i = 0; i < 8; ++i)
                CP_ASYNC16(dst + i * 2048, src + i * 512);
            CP_MBAR_ARRIVE(bar + 8 * ps);
        }
        if (++ps == STAGES) { ps = 0; ep ^= 1; }

        // ---- consumer: wait chunk kc, compute ----
        MBAR_WAIT(bar + 8 * scur, fpar);

        const uint32_t* As = sm + scur * STAGE_U32;
        const uint32_t* Bs = As + TILE_U32;
#pragma unroll
        for (int ks = 0; ks < 4; ++ks) {
            uint4 Af[4], Bf[2];
#pragma unroll
            for (int b = 0; b < 4; ++b)
                Af[b] = *(const uint4*)
                    (As + ((wm * 16 + ks * 4 + b) * 32 + lane) * 4);
#pragma unroll
            for (int p = 0; p < 2; ++p)
                Bf[p] = *(const uint4*)
                    (Bs + ((((wn * 4 + ks) * 2 + p) * 32) + lane) * 4);

#pragma unroll
            for (int b = 0; b < 4; ++b) {
                const uint4 a = Af[b];
#pragma unroll
                for (int nb = 0; nb < 4; ++nb) {
                    const uint4 bf = Bf[nb >> 1];
                    const uint32_t b0v = (nb & 1) ? bf.z : bf.x;
                    const uint32_t b1v = (nb & 1) ? bf.w : bf.y;
                    MMA_F16(acc[b][nb], a, b0v, b1v);
                }
            }
        }
        __syncwarp();
        if (lane == 0) MBAR_ARRIVE(bar + 24 + 8 * scur);
        if (++scur == STAGES) { scur = 0; fpar ^= 1; }
    }

    // ---- epilogue: bias + store ----
    const int gid = lane >> 2, tig = lane & 3;
    const int m0 = mT * 128 + wm * 64;
    const int n0 = nT * 128 + wn * 32;
#pragma unroll
    for (int nb = 0; nb < 4; ++nb) {
        const int n = n0 + nb * 8 + tig * 2;
        const float2 bv = *(const float2*)(bias + n);
#pragma unroll
        for (int b = 0; b < 4; ++b) {
            const int mA = m0 + b * 16 + gid;
            float2 v0, v1;
            v0.x = acc[b][nb][0] + bv.x;
            v0.y = acc[b][nb][1] + bv.y;
            v1.x = acc[b][nb][2] + bv.x;
            v1.y = acc[b][nb][3] + bv.y;
            *(float2*)(out + (size_t)mA * OUT_DIM + n) = v0;
            *(float2*)(out + (size_t)(mA + 8) * OUT_DIM + n) = v1;
        }
    }
}

// ============================================================================
extern "C" void kernel_launch(void* const* d_in, const int* in_sizes, int n_in,
                              void* d_out, int out_size) {
    const float* x         = (const float*)d_in[0];
    const int*   packed    = (const int*)  d_in[1];
    const float* scales    = (const float*)d_in[2];
    const float* offsets   = (const float*)d_in[3];
    const float* inv_scale = (const float*)d_in[4];
    const float* bias      = (const float*)d_in[5];
    float*       out       = (float*)d_out;

    static bool attr_set = false;
    if (!attr_set) {
        cudaFuncSetAttribute(awq_mma_gemm,
                             cudaFuncAttributeMaxDynamicSharedMemorySize,
                             SMEM_BYTES);
        attr_set = true;
    }

    prep_kernel<<<W_TILES + X_TILES, 256>>>(packed, scales, offsets,
                                            inv_scale, x);

    dim3 grid(256, 22);   // 8 nT x 32 mT supertiles; 2 superrows x 11 supercols
    awq_mma_gemm<<<grid, 256, SMEM_BYTES>>>(bias, out);
}

// round 13
// speedup vs baseline: 1.2212x; 1.0192x over previous
#include <cuda_runtime.h>
#include <cuda_fp16.h>
#include <cstdint>

// ============================================================================
// AWQ int4 linear via fp16 mma.sync (m16n8k16, fp32 accumulate):
//   (1) merged prepass: DIRECT fragment-order tile construction, 8 uint4 per
//       thread for deep MLP, coalesced STG.128.
//   (2) GEMM: 128x128 CTA tiles, 8 warps (warp 64x32), k-chunk 64, 3-stage
//       cp.async pipeline with per-stage mbarriers, producer specialization
//       by half-CTA, 2 CTAs/SM, PAIRED consumer waits: full(kc+1) implies
//       full(kc) via per-thread cp.async FIFO ordering -> 32 waits, not 64.
// out[m][n] = sum_k x[m][k]*W[n][k] + bias[n]
// W[n][k] = (q[n][k]*scales[g]+offsets[g])*inv_scale[k], g = n*32 + k/128
// M=8192, N=11008, K=4096.
// ============================================================================

#define IN_DIM   4096
#define OUT_DIM  11008
#define M_DIM    8192
#define BKC      64                    // k per pipeline stage
#define NKC      (IN_DIM / BKC)        // 64 k-chunks (even -> clean pairs)
#define STAGES   3
#define TILE_U32 4096                  // one 128x64 fp16 operand tile (16KB)
#define STAGE_U32 (2 * TILE_U32)       // A tile then B tile (32KB)
#define STAGE_BYTES (STAGE_U32 * 4)
#define SMEM_BYTES (STAGES * STAGE_BYTES + 64)   // 96KB + barriers
#define MT_TILES  (M_DIM / 128)        // 64
#define NT_TILES  (OUT_DIM / 128)      // 86
#define W_TILES   (NT_TILES * NKC)     // 5504
#define X_TILES   (MT_TILES * NKC)     // 4096

// Pre-tiled fp16 operands in fragment order (static scratch; no allocs).
__device__ uint32_t g_w[(size_t)W_TILES * TILE_U32];   // 90 MB
__device__ uint32_t g_x[(size_t)X_TILES * TILE_U32];   // 67 MB

__device__ __forceinline__ uint32_t smem_u32(const void* p) {
    uint32_t a;
    asm("{ .reg .u64 t; cvta.to.shared.u64 t, %1; cvt.u32.u64 %0, t; }"
        : "=r"(a) : "l"(p));
    return a;
}

__device__ __forceinline__ uint32_t pack_h2(float lo, float hi) {
    __half2 h = __floats2half2_rn(lo, hi);   // .x = lo half
    return *(uint32_t*)&h;
}

// ---- mbarrier / cp.async primitives ----
#define MBAR_INIT(a, c) \
    asm volatile("mbarrier.init.shared.b64 [%0], %1;" :: "r"(a), "r"(c) : "memory")
#define MBAR_ARRIVE(a) \
    asm volatile("mbarrier.arrive.shared.b64 _, [%0];" :: "r"(a) : "memory")
#define CP_MBAR_ARRIVE(a) \
    asm volatile("cp.async.mbarrier.arrive.noinc.shared.b64 [%0];" \
                 :: "r"(a) : "memory")
#define MBAR_WAIT(a, ph) do {                                                  \
    uint32_t _m = (a), _p = (uint32_t)(ph), _d;                                \
    asm volatile("{\n\t.reg .pred p;\n\t"                                      \
        "mbarrier.try_wait.parity.acquire.cta.shared::cta.b64 p, [%1], %2;\n\t"\
        "selp.b32 %0, 1, 0, p;\n\t}" : "=r"(_d) : "r"(_m), "r"(_p) : "memory");\
    if (!_d) {                                                                 \
        asm volatile("{\n\t.reg .pred P1;\n\t"                                 \
            "W%=:\n\t"                                                         \
            "mbarrier.try_wait.parity.acquire.cta.shared::cta.b64 P1, [%0], %1, 0x989680;\n\t" \
            "@P1 bra.uni D%=;\n\t"                                             \
            "bra.uni W%=;\n\t"                                                 \
            "D%=:\n\t}" :: "r"(_m), "r"(_p) : "memory");                       \
    }                                                                          \
} while (0)

#define CP_ASYNC16(dst, src)                                                   \
    asm volatile("cp.async.cg.shared.global.L2::256B [%0], [%1], 16;"          \
                 :: "r"(dst), "l"(src) : "memory")

#define MMA_F16(c, a, b0v, b1v)                                                \
    asm volatile("mma.sync.aligned.m16n8k16.row.col.f32.f16.f16.f32 "          \
        "{%0,%1,%2,%3}, {%4,%5,%6,%7}, {%8,%9}, {%0,%1,%2,%3};"                \
        : "+f"((c)[0]), "+f"((c)[1]), "+f"((c)[2]), "+f"((c)[3])               \
        : "r"((a).x), "r"((a).y), "r"((a).z), "r"((a).w),                      \
          "r"(b0v), "r"(b1v))

// ============================================================================
// Merged prepass, direct construction, 128 threads x 8 uint4 per tile.
// ============================================================================
__global__ __launch_bounds__(128)
void prep_kernel(const int* __restrict__ packed,
                 const float* __restrict__ scales,
                 const float* __restrict__ offsets,
                 const float* __restrict__ inv,
                 const float* __restrict__ x) {
    const int tid = threadIdx.x;

    if (blockIdx.x < W_TILES) {
        const int tile = blockIdx.x;           // nT * NKC + kc
        const int nT = tile / NKC, kc = tile % NKC;
        const int kb = kc * 64;
        uint4* dst = (uint4*)(g_w + (size_t)tile * TILE_U32);
#pragma unroll
        for (int q = 0; q < 8; ++q) {
            const int u = q * 128 + tid;
            const int vec = u >> 5, lane = u & 31;
            const int wn = vec >> 3, ks = (vec >> 1) & 3, p = vec & 1;
            const int gid = lane >> 2, tig = lane & 3;
            const int kk0 = ks * 16 + tig * 2;
            const int kk1 = kk0 + 8;
            const int n0 = nT * 128 + wn * 32 + p * 16 + gid;
            const int n1 = n0 + 8;
            const int gr0 = (n0 << 5) + (kc >> 1);
            const int gr1 = (n1 << 5) + (kc >> 1);
            const float s0 = __ldg(scales + gr0), o0 = __ldg(offsets + gr0);
            const float s1 = __ldg(scales + gr1), o1 = __ldg(offsets + gr1);
            const int u00 = __ldg(packed + (size_t)n0 * 2048 + ((kb + kk0) >> 1));
            const int u01 = __ldg(packed + (size_t)n0 * 2048 + ((kb + kk1) >> 1));
            const int u10 = __ldg(packed + (size_t)n1 * 2048 + ((kb + kk0) >> 1));
            const int u11 = __ldg(packed + (size_t)n1 * 2048 + ((kb + kk1) >> 1));
            const float2 i0 = *(const float2*)(inv + kb + kk0);
            const float2 i1 = *(const float2*)(inv + kb + kk1);
            uint4 o;
            o.x = pack_h2(fmaf((float)(u00 & 15), s0, o0) * i0.x,
                          fmaf((float)((u00 >> 4) & 15), s0, o0) * i0.y);
            o.y = pack_h2(fmaf((float)(u01 & 15), s0, o0) * i1.x,
                          fmaf((float)((u01 >> 4) & 15), s0, o0) * i1.y);
            o.z = pack_h2(fmaf((float)(u10 & 15), s1, o1) * i0.x,
                          fmaf((float)((u10 >> 4) & 15), s1, o1) * i0.y);
            o.w = pack_h2(fmaf((float)(u11 & 15), s1, o1) * i1.x,
                          fmaf((float)((u11 >> 4) & 15), s1, o1) * i1.y);
            dst[u] = o;
        }
    } else {
        const int tile = blockIdx.x - W_TILES;   // mT * NKC + kc
        const int mT = tile / NKC, kc = tile % NKC;
        const int kb = kc * 64;
        uint4* dst = (uint4*)(g_x + (size_t)tile * TILE_U32);
#pragma unroll
        for (int q = 0; q < 8; ++q) {
            const int u = q * 128 + tid;
            const int vec = u >> 5, lane = u & 31;
            const int wm = vec >> 4, ks = (vec >> 2) & 3, b = vec & 3;
            const int gid = lane >> 2, tig = lane & 3;
            const int kk0 = ks * 16 + tig * 2;
            const int kk1 = kk0 + 8;
            const int m0 = mT * 128 + wm * 64 + b * 16 + gid;
            const int m1 = m0 + 8;
            const float2 x00 = *(const float2*)(x + (size_t)m0 * IN_DIM + kb + kk0);
            const float2 x01 = *(const float2*)(x + (size_t)m0 * IN_DIM + kb + kk1);
            const float2 x10 = *(const float2*)(x + (size_t)m1 * IN_DIM + kb + kk0);
            const float2 x11 = *(const float2*)(x + (size_t)m1 * IN_DIM + kb + kk1);
            uint4 o;
            o.x = pack_h2(x00.x, x00.y);
            o.y = pack_h2(x10.x, x10.y);
            o.z = pack_h2(x01.x, x01.y);
            o.w = pack_h2(x11.x, x11.y);
            dst[u] = o;
        }
    }
}

// ============================================================================
// Main GEMM: 128x128 per CTA, 256 threads, warp 64x32, mbarrier pipeline,
// producer specialization, paired consumer waits.
// ============================================================================
__device__ __forceinline__ void compute_chunk(
    const uint32_t* As, const uint32_t* Bs, int wm, int wn, int lane,
    float acc[4][4][4]) {
#pragma unroll
    for (int ks = 0; ks < 4; ++ks) {
        uint4 Af[4], Bf[2];
#pragma unroll
        for (int b = 0; b < 4; ++b)
            Af[b] = *(const uint4*)
                (As + ((wm * 16 + ks * 4 + b) * 32 + lane) * 4);
#pragma unroll
        for (int p = 0; p < 2; ++p)
            Bf[p] = *(const uint4*)
                (Bs + ((((wn * 4 + ks) * 2 + p) * 32) + lane) * 4);

#pragma unroll
        for (int b = 0; b < 4; ++b) {
            const uint4 a = Af[b];
#pragma unroll
            for (int nb = 0; nb < 4; ++nb) {
                const uint4 bf = Bf[nb >> 1];
                const uint32_t b0v = (nb & 1) ? bf.z : bf.x;
                const uint32_t b1v = (nb & 1) ? bf.w : bf.y;
                MMA_F16(acc[b][nb], a, b0v, b1v);
            }
        }
    }
}

__global__ __launch_bounds__(256, 2)
void awq_mma_gemm(const float* __restrict__ bias, float* __restrict__ out) {
    extern __shared__ uint32_t sm[];
    const int tid  = threadIdx.x;
    const int lane = tid & 31;
    const int wid  = tid >> 5;
    const int wm   = wid >> 2;      // m 64-half
    const int wn   = wid & 3;       // n 32-quarter

    // supertile raster: grid(256, 22); x: 8 nT x 32 mT inside a supertile
    const int sc  = blockIdx.y % 11;
    const int smr = blockIdx.y / 11;
    const int nT  = sc * 8 + (blockIdx.x & 7);
    const int mT  = smr * 32 + (blockIdx.x >> 3);
    if (nT >= NT_TILES) return;

    const uint32_t* aSrc = g_x + (size_t)mT * NKC * TILE_U32;
    const uint32_t* bSrc = g_w + (size_t)nT * NKC * TILE_U32;
    const uint32_t sb  = smem_u32(sm);
    const uint32_t bar = sb + STAGES * STAGE_BYTES;   // full[s]=+8s, empty=+24+8s

    // producer role (fixed per thread): lower half copies A, upper half B.
    const int   pl      = tid & 127;
    const bool  isA     = tid < 128;
    const uint32_t* gBase = (isA ? aSrc : bSrc) + pl * 4;   // + chunk*TILE_U32
    const uint32_t dOff = (isA ? pl : 1024 + pl) * 16;

    if (tid == 0) {
#pragma unroll
        for (int s = 0; s < STAGES; ++s) {
            MBAR_INIT(bar + 8 * s, 256);       // full: one cp-arrive per thread
            MBAR_INIT(bar + 24 + 8 * s, 8);    // empty: one arrive per warp
        }
    }
    __syncthreads();

    float acc[4][4][4];
#pragma unroll
    for (int b = 0; b < 4; ++b)
#pragma unroll
        for (int nb = 0; nb < 4; ++nb)
#pragma unroll
            for (int i = 0; i < 4; ++i) acc[b][nb][i] = 0.0f;

    // ---- prologue: fill stages 0..STAGES-2 (chunks 0,1) ----
#pragma unroll
    for (int s = 0; s < STAGES - 1; ++s) {
        const uint32_t dst = sb + s * STAGE_BYTES + dOff;
        const uint32_t* src = gBase + (size_t)s * TILE_U32;
#pragma unroll
        for (int i = 0; i < 8; ++i)
            CP_ASYNC16(dst + i * 2048, src + i * 512);
        CP_MBAR_ARRIVE(bar + 8 * s);
    }

    int scur = 0, fpar = 0;        // consumer cursor for chunk kc
    int ps = STAGES - 1, ep = 1;   // producer cursor (advances 1 per chunk)
#pragma unroll 1
    for (int kc = 0; kc < NKC; kc += 2) {
        // cursor for kc+1
        int s1 = scur + 1, f1 = fpar;
        if (s1 == STAGES) { s1 = 0; f1 ^= 1; }

        // ---- produce chunk kc+2 into stage ps ----
        {
            const int pc = kc + 2;
            if (pc < NKC) {
                if (pc >= STAGES) MBAR_WAIT(bar + 24 + 8 * ps, ep);
                const uint32_t dst = sb + ps * STAGE_BYTES + dOff;
                const uint32_t* src = gBase + (size_t)pc * TILE_U32;
#pragma unroll
                for (int i = 0; i < 8; ++i)
                    CP_ASYNC16(dst + i * 2048, src + i * 512);
                CP_MBAR_ARRIVE(bar + 8 * ps);
            }
            if (++ps == STAGES) { ps = 0; ep ^= 1; }
        }

        // ---- single wait covers chunks kc and kc+1 (cp.async FIFO order) ----
        MBAR_WAIT(bar + 8 * s1, f1);

        // ---- compute chunk kc ----
        compute_chunk(sm + scur * STAGE_U32, sm + scur * STAGE_U32 + TILE_U32,
                      wm, wn, lane, acc);
        if (lane == 0) MBAR_ARRIVE(bar + 24 + 8 * scur);

        // ---- produce chunk kc+3 into stage ps (needs empty(kc): just arrived) ----
        {
            const int pc = kc + 3;
            if (pc < NKC) {
                MBAR_WAIT(bar + 24 + 8 * ps, ep);
                const uint32_t dst = sb + ps * STAGE_BYTES + dOff;
                const uint32_t* src = gBase + (size_t)pc * TILE_U32;
#pragma unroll
                for (int i = 0; i < 8; ++i)
                    CP_ASYNC16(dst + i * 2048, src + i * 512);
                CP_MBAR_ARRIVE(bar + 8 * ps);
            }
            if (++ps == STAGES) { ps = 0; ep ^= 1; }
        }

        // ---- compute chunk kc+1 ----
        compute_chunk(sm + s1 * STAGE_U32, sm + s1 * STAGE_U32 + TILE_U32,
                      wm, wn, lane, acc);
        if (lane == 0) MBAR_ARRIVE(bar + 24 + 8 * s1);

        // advance consumer cursor past the pair
        scur = s1 + 1; fpar = f1;
        if (scur == STAGES) { scur = 0; fpar ^= 1; }
    }

    // ---- epilogue: bias + store ----
    const int gid = lane >> 2, tig = lane & 3;
    const int m0 = mT * 128 + wm * 64;
    const int n0 = nT * 128 + wn * 32;
#pragma unroll
    for (int nb = 0; nb < 4; ++nb) {
        const int n = n0 + nb * 8 + tig * 2;
        const float2 bv = *(const float2*)(bias + n);
#pragma unroll
        for (int b = 0; b < 4; ++b) {
            const int mA = m0 + b * 16 + gid;
            float2 v0, v1;
            v0.x = acc[b][nb][0] + bv.x;
            v0.y = acc[b][nb][1] + bv.y;
            v1.x = acc[b][nb][2] + bv.x;
            v1.y = acc[b][nb][3] + bv.y;
            *(float2*)(out + (size_t)mA * OUT_DIM + n) = v0;
            *(float2*)(out + (size_t)(mA + 8) * OUT_DIM + n) = v1;
        }
    }
}

// ============================================================================
extern "C" void kernel_launch(void* const* d_in, const int* in_sizes, int n_in,
                              void* d_out, int out_size) {
    const float* x         = (const float*)d_in[0];
    const int*   packed    = (const int*)  d_in[1];
    const float* scales    = (const float*)d_in[2];
    const float* offsets   = (const float*)d_in[3];
    const float* inv_scale = (const float*)d_in[4];
    const float* bias      = (const float*)d_in[5];
    float*       out       = (float*)d_out;

    static bool attr_set = false;
    if (!attr_set) {
        cudaFuncSetAttribute(awq_mma_gemm,
                             cudaFuncAttributeMaxDynamicSharedMemorySize,
                             SMEM_BYTES);
        attr_set = true;
    }

    prep_kernel<<<W_TILES + X_TILES, 128>>>(packed, scales, offsets,
                                            inv_scale, x);

    dim3 grid(256, 22);   // 8 nT x 32 mT supertiles; 2 superrows x 11 supercols
    awq_mma_gemm<<<grid, 256, SMEM_BYTES>>>(bias, out);
}